// round 4
// baseline (speedup 1.0000x reference)
#include <cuda_runtime.h>
#include <math.h>

#define NB 4
#define NC 64
#define NH 96
#define NW 320
#define NHC 97            // CF rows 0..96
#define NHO 113           // 97 CF rows + 16 R0 special rows
#define MTOT (NHO*NW)     // 36160 pixels per batch image (113*320)

// Scratch (static device arrays; no runtime allocation)
__device__ float g_X0[NB*NH*NW*NC];     // NHWC input / final NHWC output
__device__ float g_X1[NB*NH*NW*NC];     // layer-1 NHWC output
__device__ float g_CF[(size_t)NB*NHO*NW*NC];    // conv output (CF + R0 rows)
__device__ float g_Wt[2][9*NC*NC];      // transformed weights [tap][ci][co]

__device__ __forceinline__ void plane_shift(int d, int& o, float& w){
    // disp = linspace(1/50, 1, 8) in f32 ; shift = 76 * disp
    float step = (1.0f - (1.0f/50.0f)) / 7.0f;
    float s = 76.0f * ((1.0f/50.0f) + (float)d * step);
    float fo = floorf(s);
    o = (int)fo;
    w = s - fo;
}

// ---- weight transform: W[co][ci][3][3] -> Wt[tap][ci][co] ----
__global__ void k_wt(const float* __restrict__ W, int sel){
    int i = blockIdx.x*256 + threadIdx.x;
    if(i >= 9*NC*NC) return;
    int co = i & 63, ci = (i>>6) & 63, tap = i >> 12;
    g_Wt[sel][i] = W[(co*NC + ci)*9 + tap];
}

// ---- NCHW -> NHWC (into g_X0) ----
__global__ void k_nchw2nhwc(const float* __restrict__ in){
    __shared__ float t[32][33];
    int b = blockIdx.z / NH, r = blockIdx.z % NH;
    int c0 = blockIdx.x*32, q0 = blockIdx.y*32;
    int tx = threadIdx.x, ty = threadIdx.y;
    #pragma unroll
    for(int j=0;j<32;j+=8)
        t[ty+j][tx] = in[((size_t)(b*NC + q0+ty+j)*NH + r)*NW + c0+tx];
    __syncthreads();
    #pragma unroll
    for(int j=0;j<32;j+=8)
        g_X0[((size_t)(b*NH + r)*NW + c0+ty+j)*NC + q0+tx] = t[tx][ty+j];
}

// ---- NHWC (g_X0) -> NCHW (d_out) ----
__global__ void k_nhwc2nchw(float* __restrict__ out){
    __shared__ float t[32][33];
    int b = blockIdx.z / NH, r = blockIdx.z % NH;
    int c0 = blockIdx.x*32, q0 = blockIdx.y*32;
    int tx = threadIdx.x, ty = threadIdx.y;
    #pragma unroll
    for(int j=0;j<32;j+=8)
        t[ty+j][tx] = g_X0[((size_t)(b*NH + r)*NW + c0+ty+j)*NC + q0+tx];
    __syncthreads();
    #pragma unroll
    for(int j=0;j<32;j+=8)
        out[((size_t)(b*NC + q0+ty+j)*NH + r)*NW + c0+tx] = t[tx][ty+j];
}

// ---- implicit-GEMM conv: CF[t] = conv3x3(xz) for t in [0,96], rows 97..112 = R0 specials ----
// M = 113*320 pixels per batch, N = 64 co, K = 576 (tap-major: k = tap*64 + ci)
__global__ void __launch_bounds__(128) k_conv(int inSel, int wSel){
    __shared__ float As[2][16][128];
    __shared__ float Bs[2][16][64];

    const float* __restrict__ X  = (inSel ? g_X1 : g_X0) + (size_t)blockIdx.y*(NH*NW*NC);
    const float* __restrict__ Wt = g_Wt[wSel];
    float* __restrict__ CF = g_CF + (size_t)blockIdx.y*(NHO*NW*NC);

    int m0  = blockIdx.x * 128;
    int tid = threadIdx.x;
    int tm = tid >> 3, tn = tid & 7;
    int lp  = tid >> 2;          // gather pixel lane 0..31
    int ciq = (tid & 3) * 4;     // ci quad within 16-chunk

    // per-pixel row spec for the 4 gather pixels of this thread
    int pbase[4], pmask[4], pcol[4];
    #pragma unroll
    for(int p=0;p<4;p++){
        int m = m0 + p*32 + lp;
        if(m >= MTOT){ pmask[p]=0; pbase[p]=0; pcol[p]=0; }
        else {
            int row = m / NW, col = m - row*NW;
            pcol[p] = col;
            if(row < NHC){ pbase[p] = row - 1; pmask[p] = 7; }      // normal conv row
            else {                                                   // R0 special row
                int i = row - NHC; int d = i >> 1;
                int o; float w; plane_shift(d, o, w);
                pbase[p] = (i & 1) ? o : o - 1;                      // target x row t
                pmask[p] = 1;                                        // only tap-row dy==0
            }
        }
    }

    float acc[8][8];
    #pragma unroll
    for(int i=0;i<8;i++)
        #pragma unroll
        for(int j=0;j<8;j++) acc[i][j]=0.f;

    float4 ra[4]; float4 rb0, rb1;

    auto gather = [&](int kc){
        int tap = kc >> 2, ci0 = (kc & 3) << 4;
        int dy = tap / 3, dx = tap - dy*3;
        #pragma unroll
        for(int p=0;p<4;p++){
            int rr = pbase[p] + dy;
            int cc = pcol[p] + dx - 1;
            bool v = ((pmask[p] >> dy) & 1) && ((unsigned)rr < NH) && ((unsigned)cc < NW);
            if(v) ra[p] = *(const float4*)&X[((size_t)rr*NW + cc)*NC + ci0 + ciq];
            else  ra[p] = make_float4(0.f,0.f,0.f,0.f);
        }
        const float4* wp = (const float4*)&Wt[(tap*64 + ci0)*64];
        rb0 = wp[tid*2]; rb1 = wp[tid*2 + 1];
    };
    auto storebuf = [&](int bsel){
        #pragma unroll
        for(int p=0;p<4;p++){
            int px = p*32 + lp;
            As[bsel][ciq+0][px] = ra[p].x;
            As[bsel][ciq+1][px] = ra[p].y;
            As[bsel][ciq+2][px] = ra[p].z;
            As[bsel][ciq+3][px] = ra[p].w;
        }
        float4* bp = (float4*)&Bs[bsel][0][0];
        bp[tid*2] = rb0; bp[tid*2 + 1] = rb1;
    };

    gather(0);
    storebuf(0);
    __syncthreads();

    int buf = 0;
    for(int kc=0; kc<36; kc++){
        if(kc < 35) gather(kc+1);
        #pragma unroll
        for(int k=0;k<16;k++){
            float4 a0 = *(const float4*)&As[buf][k][tm*8];
            float4 a1 = *(const float4*)&As[buf][k][tm*8 + 4];
            float4 b0 = *(const float4*)&Bs[buf][k][tn*8];
            float4 b1 = *(const float4*)&Bs[buf][k][tn*8 + 4];
            float av[8] = {a0.x,a0.y,a0.z,a0.w,a1.x,a1.y,a1.z,a1.w};
            float bv[8] = {b0.x,b0.y,b0.z,b0.w,b1.x,b1.y,b1.z,b1.w};
            #pragma unroll
            for(int i=0;i<8;i++)
                #pragma unroll
                for(int j=0;j<8;j++)
                    acc[i][j] += av[i]*bv[j];
        }
        if(kc < 35){
            __syncthreads();
            storebuf(buf ^ 1);
            __syncthreads();
            buf ^= 1;
        }
    }

    #pragma unroll
    for(int i=0;i<8;i++){
        int m = m0 + tm*8 + i;
        if(m < MTOT){
            float* o = &CF[(size_t)m*NC + tn*8];
            *(float4*)(o)   = make_float4(acc[i][0],acc[i][1],acc[i][2],acc[i][3]);
            *(float4*)(o+4) = make_float4(acc[i][4],acc[i][5],acc[i][6],acc[i][7]);
        }
    }
}

// ---- epilogue: 8-plane blend + max + bias + relu, NHWC output ----
__global__ void k_epi(const float* __restrict__ bias, int outSel){
    int tid = threadIdx.x;
    int co = tid & 63;
    int c  = blockIdx.x*4 + (tid >> 6);
    int y  = blockIdx.y;
    int b  = blockIdx.z;
    const float* cf = g_CF + (size_t)b*NHO*NW*NC;

    float mx = -3.4e38f;
    #pragma unroll
    for(int d=0; d<8; d++){
        int o; float w; plane_shift(d, o, w);
        float a = 1.0f - w;
        int t = y + o;
        float v = 0.f;
        if(t <= 96)     v += a * cf[((size_t)t*NW + c)*NC + co];
        if(t + 1 <= 96) v += w * cf[((size_t)(t+1)*NW + c)*NC + co];
        if(y == 0){
            v -= a * cf[((size_t)(97 + 2*d)*NW + c)*NC + co];   // R0[o_d - 1]
            v -= w * cf[((size_t)(98 + 2*d)*NW + c)*NC + co];   // R0[o_d]
        }
        mx = fmaxf(mx, v);
    }
    float r = fmaxf(mx + bias[co], 0.f);
    float* out = outSel ? g_X0 : g_X1;
    out[(((size_t)b*NH + y)*NW + c)*NC + co] = r;
}

extern "C" void kernel_launch(void* const* d_in, const int* in_sizes, int n_in,
                              void* d_out, int out_size){
    const float* x  = (const float*)d_in[0];
    const float* W1 = (const float*)d_in[1];
    const float* b1 = (const float*)d_in[2];
    const float* W2 = (const float*)d_in[3];
    const float* b2 = (const float*)d_in[4];
    float* out = (float*)d_out;

    k_wt<<<144, 256>>>(W1, 0);
    k_wt<<<144, 256>>>(W2, 1);
    k_nchw2nhwc<<<dim3(10,2,NB*NH), dim3(32,8)>>>(x);

    k_conv<<<dim3(283, NB), 128>>>(0, 0);         // X0 -> CF (layer 1)
    k_epi <<<dim3(80, NH, NB), 256>>>(b1, 0);     // CF -> X1

    k_conv<<<dim3(283, NB), 128>>>(1, 1);         // X1 -> CF (layer 2)
    k_epi <<<dim3(80, NH, NB), 256>>>(b2, 1);     // CF -> X0

    k_nhwc2nchw<<<dim3(10,2,NB*NH), dim3(32,8)>>>(out);
}

// round 7
// speedup vs baseline: 1.1228x; 1.1228x over previous
#include <cuda_runtime.h>
#include <math.h>

#define NB 4
#define NC 64
#define NH 96
#define NW 320
#define NHC 97            // CF rows 0..96
#define NHO 113           // 97 CF rows + 16 R0 special rows
#define MTOT (NHO*NW)     // 36160 pixels per batch image (113*320)

// Scratch (static device arrays; no runtime allocation)
__device__ float g_X0[NB*NH*NW*NC];     // NHWC input / final NHWC output
__device__ float g_X1[NB*NH*NW*NC];     // layer-1 NHWC output
__device__ float g_CF[(size_t)NB*NHO*NW*NC];    // conv output (CF + R0 rows)
__device__ float g_Wt[2][9*NC*NC];      // transformed weights [tap][ci][co]

__device__ __forceinline__ void plane_shift(int d, int& o, float& w){
    // disp = linspace(1/50, 1, 8) in f32 ; shift = 76 * disp
    float step = (1.0f - (1.0f/50.0f)) / 7.0f;
    float s = 76.0f * ((1.0f/50.0f) + (float)d * step);
    float fo = floorf(s);
    o = (int)fo;
    w = s - fo;
}

// ---- weight transform: W[co][ci][3][3] -> Wt[tap][ci][co] ----
__global__ void k_wt(const float* __restrict__ W, int sel){
    int i = blockIdx.x*256 + threadIdx.x;
    if(i >= 9*NC*NC) return;
    int co = i & 63, ci = (i>>6) & 63, tap = i >> 12;
    g_Wt[sel][i] = W[(co*NC + ci)*9 + tap];
}

// ---- NCHW -> NHWC (into g_X0) ----
__global__ void k_nchw2nhwc(const float* __restrict__ in){
    __shared__ float t[32][33];
    int b = blockIdx.z / NH, r = blockIdx.z % NH;
    int c0 = blockIdx.x*32, q0 = blockIdx.y*32;
    int tx = threadIdx.x, ty = threadIdx.y;
    #pragma unroll
    for(int j=0;j<32;j+=8)
        t[ty+j][tx] = in[((size_t)(b*NC + q0+ty+j)*NH + r)*NW + c0+tx];
    __syncthreads();
    #pragma unroll
    for(int j=0;j<32;j+=8)
        g_X0[((size_t)(b*NH + r)*NW + c0+ty+j)*NC + q0+tx] = t[tx][ty+j];
}

// ---- NHWC (g_X0) -> NCHW (d_out) ----
__global__ void k_nhwc2nchw(float* __restrict__ out){
    __shared__ float t[32][33];
    int b = blockIdx.z / NH, r = blockIdx.z % NH;
    int c0 = blockIdx.x*32, q0 = blockIdx.y*32;
    int tx = threadIdx.x, ty = threadIdx.y;
    #pragma unroll
    for(int j=0;j<32;j+=8)
        t[ty+j][tx] = g_X0[((size_t)(b*NH + r)*NW + c0+ty+j)*NC + q0+tx];
    __syncthreads();
    #pragma unroll
    for(int j=0;j<32;j+=8)
        out[((size_t)(b*NC + q0+ty+j)*NH + r)*NW + c0+tx] = t[tx][ty+j];
}

// ---- implicit-GEMM conv: CF[t] = conv3x3(xz) for t in [0,96], rows 97..112 = R0 specials ----
// M = 113*320 pixels per batch, N = 64 co, K = 576 (tap-major: k = tap*64 + ci)
// A-tile in smem is XOR-swizzled: physical col = px ^ ((row>>2)*8)  (conflict-free STS + LDS.128 reads)
__global__ void __launch_bounds__(128) k_conv(int inSel, int wSel){
    __shared__ float As[2][16][128];
    __shared__ float Bs[2][16][64];

    const float* __restrict__ X  = (inSel ? g_X1 : g_X0) + (size_t)blockIdx.y*(NH*NW*NC);
    const float* __restrict__ Wt = g_Wt[wSel];
    float* __restrict__ CF = g_CF + (size_t)blockIdx.y*(NHO*NW*NC);

    int m0  = blockIdx.x * 128;
    int tid = threadIdx.x;
    int tm = tid >> 3, tn = tid & 7;
    int lp  = tid >> 2;          // gather pixel lane 0..31
    int ciq = (tid & 3) * 4;     // ci quad within 16-chunk
    int swz = (tid & 3) * 8;     // store-side XOR swizzle ( == (row>>2)*8 for rows ciq..ciq+3 )

    // per-pixel row spec for the 4 gather pixels of this thread
    int pbase[4], pmask[4], pcol[4], pxs[4];
    #pragma unroll
    for(int p=0;p<4;p++){
        int m = m0 + p*32 + lp;
        pxs[p] = (p*32 + lp) ^ swz;
        if(m >= MTOT){ pmask[p]=0; pbase[p]=0; pcol[p]=0; }
        else {
            int row = m / NW, col = m - row*NW;
            pcol[p] = col;
            if(row < NHC){ pbase[p] = row - 1; pmask[p] = 7; }      // normal conv row
            else {                                                   // R0 special row
                int i = row - NHC; int d = i >> 1;
                int o; float w; plane_shift(d, o, w);
                pbase[p] = (i & 1) ? o : o - 1;                      // target x row t
                pmask[p] = 1;                                        // only tap-row dy==0
            }
        }
    }

    // accumulators: pairs along m. acc[mp][j] = (C[2mp][j], C[2mp+1][j]) packed f32x2
    unsigned long long acc[4][8];
    #pragma unroll
    for(int i=0;i<4;i++)
        #pragma unroll
        for(int j=0;j<8;j++) acc[i][j] = 0ull;

    float4 ra[4]; float4 rb0, rb1;

    auto gather = [&](int kc){
        int tap = kc >> 2, ci0 = (kc & 3) << 4;
        int dy = tap / 3, dx = tap - dy*3;
        #pragma unroll
        for(int p=0;p<4;p++){
            int rr = pbase[p] + dy;
            int cc = pcol[p] + dx - 1;
            bool v = ((pmask[p] >> dy) & 1) && ((unsigned)rr < NH) && ((unsigned)cc < NW);
            if(v) ra[p] = *(const float4*)&X[((size_t)rr*NW + cc)*NC + ci0 + ciq];
            else  ra[p] = make_float4(0.f,0.f,0.f,0.f);
        }
        const float4* wp = (const float4*)&Wt[(tap*64 + ci0)*64];
        rb0 = wp[tid*2]; rb1 = wp[tid*2 + 1];
    };
    auto storebuf = [&](int bsel){
        #pragma unroll
        for(int p=0;p<4;p++){
            int px = pxs[p];
            As[bsel][ciq+0][px] = ra[p].x;
            As[bsel][ciq+1][px] = ra[p].y;
            As[bsel][ciq+2][px] = ra[p].z;
            As[bsel][ciq+3][px] = ra[p].w;
        }
        float4* bp = (float4*)&Bs[bsel][0][0];
        bp[tid*2] = rb0; bp[tid*2 + 1] = rb1;
    };

    gather(0);
    storebuf(0);
    __syncthreads();

    int buf = 0;
    for(int kc=0; kc<36; kc++){
        if(kc < 35) gather(kc+1);
        #pragma unroll
        for(int k=0;k<16;k++){
            const float* arow = &As[buf][k][0];
            int g = (k >> 2) * 8;
            int base = (tm*8) ^ g;              // physical col of logical tm*8 (whole group XOR)
            ulonglong2 aA = *(const ulonglong2*)(arow + base);       // pairs (m0,m1),(m2,m3)
            ulonglong2 aB = *(const ulonglong2*)(arow + base + 4);   // pairs (m4,m5),(m6,m7)
            float4 b0 = *(const float4*)&Bs[buf][k][tn*8];
            float4 b1 = *(const float4*)&Bs[buf][k][tn*8 + 4];
            float bv[8] = {b0.x,b0.y,b0.z,b0.w,b1.x,b1.y,b1.z,b1.w};
            unsigned long long bb[8];
            #pragma unroll
            for(int j=0;j<8;j++){
                unsigned int u = __float_as_uint(bv[j]);
                asm("mov.b64 %0, {%1, %1};" : "=l"(bb[j]) : "r"(u));
            }
            unsigned long long ap[4] = {aA.x, aA.y, aB.x, aB.y};
            #pragma unroll
            for(int mp=0;mp<4;mp++)
                #pragma unroll
                for(int j=0;j<8;j++)
                    asm("fma.rn.f32x2 %0, %1, %2, %0;"
                        : "+l"(acc[mp][j]) : "l"(ap[mp]), "l"(bb[j]));
        }
        if(kc < 35){
            storebuf(buf ^ 1);
            __syncthreads();
            buf ^= 1;
        }
    }

    #pragma unroll
    for(int i=0;i<8;i++){
        int m = m0 + tm*8 + i;
        if(m < MTOT){
            int mp = i >> 1, hi = i & 1;
            float v[8];
            #pragma unroll
            for(int j=0;j<8;j++){
                unsigned long long a = acc[mp][j];
                unsigned int u = hi ? (unsigned int)(a >> 32) : (unsigned int)a;
                v[j] = __uint_as_float(u);
            }
            float* o = &CF[(size_t)m*NC + tn*8];
            *(float4*)(o)   = make_float4(v[0],v[1],v[2],v[3]);
            *(float4*)(o+4) = make_float4(v[4],v[5],v[6],v[7]);
        }
    }
}

// ---- epilogue: 8-plane blend + max + bias + relu, NHWC output ----
__global__ void k_epi(const float* __restrict__ bias, int outSel){
    int tid = threadIdx.x;
    int co = tid & 63;
    int c  = blockIdx.x*4 + (tid >> 6);
    int y  = blockIdx.y;
    int b  = blockIdx.z;
    const float* cf = g_CF + (size_t)b*NHO*NW*NC;

    float mx = -3.4e38f;
    #pragma unroll
    for(int d=0; d<8; d++){
        int o; float w; plane_shift(d, o, w);
        float a = 1.0f - w;
        int t = y + o;
        float v = 0.f;
        if(t <= 96)     v += a * cf[((size_t)t*NW + c)*NC + co];
        if(t + 1 <= 96) v += w * cf[((size_t)(t+1)*NW + c)*NC + co];
        if(y == 0){
            v -= a * cf[((size_t)(97 + 2*d)*NW + c)*NC + co];   // R0[o_d - 1]
            v -= w * cf[((size_t)(98 + 2*d)*NW + c)*NC + co];   // R0[o_d]
        }
        mx = fmaxf(mx, v);
    }
    float r = fmaxf(mx + bias[co], 0.f);
    float* out = outSel ? g_X0 : g_X1;
    out[(((size_t)b*NH + y)*NW + c)*NC + co] = r;
}

extern "C" void kernel_launch(void* const* d_in, const int* in_sizes, int n_in,
                              void* d_out, int out_size){
    const float* x  = (const float*)d_in[0];
    const float* W1 = (const float*)d_in[1];
    const float* b1 = (const float*)d_in[2];
    const float* W2 = (const float*)d_in[3];
    const float* b2 = (const float*)d_in[4];
    float* out = (float*)d_out;

    k_wt<<<144, 256>>>(W1, 0);
    k_wt<<<144, 256>>>(W2, 1);
    k_nchw2nhwc<<<dim3(10,2,NB*NH), dim3(32,8)>>>(x);

    k_conv<<<dim3(283, NB), 128>>>(0, 0);         // X0 -> CF (layer 1)
    k_epi <<<dim3(80, NH, NB), 256>>>(b1, 0);     // CF -> X1

    k_conv<<<dim3(283, NB), 128>>>(1, 1);         // X1 -> CF (layer 2)
    k_epi <<<dim3(80, NH, NB), 256>>>(b2, 1);     // CF -> X0

    k_nhwc2nchw<<<dim3(10,2,NB*NH), dim3(32,8)>>>(out);
}

// round 13
// speedup vs baseline: 1.2831x; 1.1428x over previous
#include <cuda_runtime.h>
#include <math.h>

#define NB 4
#define NC 64
#define NH 96
#define NW 320
#define NHC 97            // CF rows 0..96
#define NHO 113           // 97 CF rows + 16 R0 special rows
#define MTOT (NHO*NW)     // 36160 pixels per batch image (113*320)
#define MTILE 256
#define MBLK ((MTOT + MTILE - 1) / MTILE)   // 142

// Scratch (static device arrays; no runtime allocation)
__device__ float g_X0[NB*NH*NW*NC];     // NHWC input / final NHWC output
__device__ float g_X1[NB*NH*NW*NC];     // layer-1 NHWC output
__device__ float g_CF[(size_t)NB*NHO*NW*NC];    // conv output (CF + R0 rows)
__device__ float g_Wt[2][9*NC*NC];      // transformed weights [tap][ci][co]

__device__ __forceinline__ void plane_shift(int d, int& o, float& w){
    // disp = linspace(1/50, 1, 8) in f32 ; shift = 76 * disp
    float step = (1.0f - (1.0f/50.0f)) / 7.0f;
    float s = 76.0f * ((1.0f/50.0f) + (float)d * step);
    float fo = floorf(s);
    o = (int)fo;
    w = s - fo;
}

// ---- weight transform: W[co][ci][3][3] -> Wt[tap][ci][co] ----
__global__ void k_wt(const float* __restrict__ W, int sel){
    int i = blockIdx.x*256 + threadIdx.x;
    if(i >= 9*NC*NC) return;
    int co = i & 63, ci = (i>>6) & 63, tap = i >> 12;
    g_Wt[sel][i] = W[(co*NC + ci)*9 + tap];
}

// ---- NCHW -> NHWC (into g_X0) ----
__global__ void k_nchw2nhwc(const float* __restrict__ in){
    __shared__ float t[32][33];
    int b = blockIdx.z / NH, r = blockIdx.z % NH;
    int c0 = blockIdx.x*32, q0 = blockIdx.y*32;
    int tx = threadIdx.x, ty = threadIdx.y;
    #pragma unroll
    for(int j=0;j<32;j+=8)
        t[ty+j][tx] = in[((size_t)(b*NC + q0+ty+j)*NH + r)*NW + c0+tx];
    __syncthreads();
    #pragma unroll
    for(int j=0;j<32;j+=8)
        g_X0[((size_t)(b*NH + r)*NW + c0+ty+j)*NC + q0+tx] = t[tx][ty+j];
}

// ---- NHWC (g_X0) -> NCHW (d_out) ----
__global__ void k_nhwc2nchw(float* __restrict__ out){
    __shared__ float t[32][33];
    int b = blockIdx.z / NH, r = blockIdx.z % NH;
    int c0 = blockIdx.x*32, q0 = blockIdx.y*32;
    int tx = threadIdx.x, ty = threadIdx.y;
    #pragma unroll
    for(int j=0;j<32;j+=8)
        t[ty+j][tx] = g_X0[((size_t)(b*NH + r)*NW + c0+ty+j)*NC + q0+tx];
    __syncthreads();
    #pragma unroll
    for(int j=0;j<32;j+=8)
        out[((size_t)(b*NC + q0+ty+j)*NH + r)*NW + c0+tx] = t[tx][ty+j];
}

// ---- implicit-GEMM conv: M-tile 256, N 64, thread tile 16x8 (FFMA2 along m) ----
// A-tile smem physical col = pixel ^ ((ci_row>>2)*8)  (conflict-free STS + grouped LDS.128)
__global__ void __launch_bounds__(128) k_conv(int inSel, int wSel){
    __shared__ float As[2][16][MTILE];
    __shared__ float Bs[2][16][64];

    const float* __restrict__ X  = (inSel ? g_X1 : g_X0) + (size_t)blockIdx.y*(NH*NW*NC);
    const float* __restrict__ Wt = g_Wt[wSel];
    float* __restrict__ CF = g_CF + (size_t)blockIdx.y*(NHO*NW*NC);

    int m0  = blockIdx.x * MTILE;
    int tid = threadIdx.x;
    int tm = tid >> 3, tn = tid & 7;     // 16 m-groups x 8 n-groups
    int lp  = tid >> 2;                  // gather group 0..31
    int ciq = (tid & 3) * 4;             // ci quad within 16-chunk
    int swz = (tid & 3) * 8;             // store-side XOR ( == (row>>2)*8 for rows ciq..ciq+3 )

    // per-pixel specs: this thread gathers pixels p_j = j*32 + lp, j=0..7
    int pbase[8], pmask[8], pcol[8];
    #pragma unroll
    for(int j=0;j<8;j++){
        int m = m0 + j*32 + lp;
        if(m >= MTOT){ pmask[j]=0; pbase[j]=0; pcol[j]=0; }
        else {
            int row = m / NW, col = m - row*NW;
            pcol[j] = col;
            if(row < NHC){ pbase[j] = row - 1; pmask[j] = 7; }      // normal conv row
            else {                                                   // R0 special row
                int i = row - NHC; int d = i >> 1;
                int o; float w; plane_shift(d, o, w);
                pbase[j] = (i & 1) ? o : o - 1;                      // target x row t
                pmask[j] = 1;                                        // only tap-row dy==0
            }
        }
    }

    // accumulators: pairs along m. acc[mp][j] = (C[2mp], C[2mp+1]) for co j, packed f32x2
    unsigned long long acc[8][8];
    #pragma unroll
    for(int i=0;i<8;i++)
        #pragma unroll
        for(int j=0;j<8;j++) acc[i][j] = 0ull;

    float4 ra[8]; float4 rb0, rb1;

    auto gather = [&](int kc){
        int tap = kc >> 2, ci0 = (kc & 3) << 4;
        int dy = tap / 3, dx = tap - dy*3;
        #pragma unroll
        for(int j=0;j<8;j++){
            int rr = pbase[j] + dy;
            int cc = pcol[j] + dx - 1;
            bool v = ((pmask[j] >> dy) & 1) && ((unsigned)rr < NH) && ((unsigned)cc < NW);
            if(v) ra[j] = *(const float4*)&X[((size_t)rr*NW + cc)*NC + ci0 + ciq];
            else  ra[j] = make_float4(0.f,0.f,0.f,0.f);
        }
        const float4* wp = (const float4*)&Wt[(tap*64 + ci0)*64];
        rb0 = wp[tid*2]; rb1 = wp[tid*2 + 1];
    };
    auto storebuf = [&](int bsel){
        #pragma unroll
        for(int j=0;j<8;j++){
            int px = (j*32 + lp) ^ swz;
            As[bsel][ciq+0][px] = ra[j].x;
            As[bsel][ciq+1][px] = ra[j].y;
            As[bsel][ciq+2][px] = ra[j].z;
            As[bsel][ciq+3][px] = ra[j].w;
        }
        float4* bp = (float4*)&Bs[bsel][0][0];
        bp[tid*2] = rb0; bp[tid*2 + 1] = rb1;
    };

    gather(0);
    storebuf(0);
    __syncthreads();

    int buf = 0;
    for(int kc=0; kc<36; kc++){
        if(kc < 35) gather(kc+1);
        #pragma unroll
        for(int k=0;k<16;k++){
            const float* arow = &As[buf][k][0];
            int g = (k >> 2) * 8;
            unsigned long long ap[8];
            #pragma unroll
            for(int q=0;q<4;q++){
                // XOR applied per 4-float group (q*4 and g can share bit 3)
                ulonglong2 t = *(const ulonglong2*)(arow + (((tm*16) + q*4) ^ g));
                ap[q*2]   = t.x;
                ap[q*2+1] = t.y;
            }
            float4 b0 = *(const float4*)&Bs[buf][k][tn*8];
            float4 b1 = *(const float4*)&Bs[buf][k][tn*8 + 4];
            float bv[8] = {b0.x,b0.y,b0.z,b0.w,b1.x,b1.y,b1.z,b1.w};
            #pragma unroll
            for(int j=0;j<8;j++){
                unsigned long long bb;
                unsigned int u = __float_as_uint(bv[j]);
                asm("mov.b64 %0, {%1, %1};" : "=l"(bb) : "r"(u));
                #pragma unroll
                for(int mp=0;mp<8;mp++)
                    asm("fma.rn.f32x2 %0, %1, %2, %0;"
                        : "+l"(acc[mp][j]) : "l"(ap[mp]), "l"(bb));
            }
        }
        if(kc < 35){
            storebuf(buf ^ 1);
            __syncthreads();
            buf ^= 1;
        }
    }

    #pragma unroll
    for(int i=0;i<16;i++){
        int m = m0 + tm*16 + i;
        if(m < MTOT){
            int mp = i >> 1, hi = i & 1;
            float v[8];
            #pragma unroll
            for(int j=0;j<8;j++){
                unsigned long long a = acc[mp][j];
                unsigned int u = hi ? (unsigned int)(a >> 32) : (unsigned int)a;
                v[j] = __uint_as_float(u);
            }
            float* o = &CF[(size_t)m*NC + tn*8];
            *(float4*)(o)   = make_float4(v[0],v[1],v[2],v[3]);
            *(float4*)(o+4) = make_float4(v[4],v[5],v[6],v[7]);
        }
    }
}

// ---- epilogue: 8-plane blend + max + bias + relu ----
// block = (col, batch); 256 threads = 64 co x 4 y-lanes; walks all 96 y (L1 reuse of CF rows)
__global__ void k_epi(const float* __restrict__ bias, int outSel){
    int tid = threadIdx.x;
    int co = tid & 63;
    int yl = tid >> 6;
    int c  = blockIdx.x;
    int b  = blockIdx.y;
    const float* __restrict__ cf = g_CF + (size_t)b*NHO*NW*NC + (size_t)c*NC + co;
    float bv = bias[co];
    const int rstride = NW*NC;
    float* __restrict__ out = outSel ? g_X0 : g_X1;

    for(int y = yl; y < NH; y += 4){
        float mx = -3.4e38f;
        #pragma unroll
        for(int d=0; d<8; d++){
            int o; float w; plane_shift(d, o, w);
            float a = 1.0f - w;
            int t = y + o;
            float v = 0.f;
            if(t <= 96)     v += a * cf[(size_t)t*rstride];
            if(t + 1 <= 96) v += w * cf[(size_t)(t+1)*rstride];
            if(y == 0){
                v -= a * cf[(size_t)(97 + 2*d)*rstride];   // R0[o_d - 1]
                v -= w * cf[(size_t)(98 + 2*d)*rstride];   // R0[o_d]
            }
            mx = fmaxf(mx, v);
        }
        float r = fmaxf(mx + bv, 0.f);
        out[(((size_t)b*NH + y)*NW + c)*NC + co] = r;
    }
}

extern "C" void kernel_launch(void* const* d_in, const int* in_sizes, int n_in,
                              void* d_out, int out_size){
    const float* x  = (const float*)d_in[0];
    const float* W1 = (const float*)d_in[1];
    const float* b1 = (const float*)d_in[2];
    const float* W2 = (const float*)d_in[3];
    const float* b2 = (const float*)d_in[4];
    float* out = (float*)d_out;

    k_wt<<<144, 256>>>(W1, 0);
    k_wt<<<144, 256>>>(W2, 1);
    k_nchw2nhwc<<<dim3(10,2,NB*NH), dim3(32,8)>>>(x);

    k_conv<<<dim3(MBLK, NB), 128>>>(0, 0);        // X0 -> CF (layer 1)
    k_epi <<<dim3(NW, NB), 256>>>(b1, 0);         // CF -> X1

    k_conv<<<dim3(MBLK, NB), 128>>>(1, 1);        // X1 -> CF (layer 2)
    k_epi <<<dim3(NW, NB), 256>>>(b2, 1);         // CF -> X0

    k_nhwc2nchw<<<dim3(10,2,NB*NH), dim3(32,8)>>>(out);
}

// round 14
// speedup vs baseline: 1.2894x; 1.0049x over previous
#include <cuda_runtime.h>
#include <math.h>

#define NB 4
#define NC 64
#define NH 96
#define NW 320
#define NHC 97            // CF rows 0..96
#define NHO 113           // 97 CF rows + 16 R0 special rows
#define MTOT (NHO*NW)     // 36160 pixels per batch image (113*320)
#define MTILE 192
#define MBLK ((MTOT + MTILE - 1) / MTILE)   // 189

// Scratch (static device arrays; no runtime allocation)
__device__ float g_X0[NB*NH*NW*NC];     // NHWC input / final NHWC output
__device__ float g_X1[NB*NH*NW*NC];     // layer-1 NHWC output
__device__ float g_CF[(size_t)NB*NHO*NW*NC];    // conv output (CF + R0 rows)
__device__ float g_Wt[2][9*NC*NC];      // transformed weights [tap][ci][co]

__device__ __forceinline__ unsigned smem_u32(const void* p){
    unsigned a; asm("{ .reg .u64 t; cvta.to.shared.u64 t, %1; cvt.u32.u64 %0, t; }" : "=r"(a) : "l"(p));
    return a;
}

__device__ __forceinline__ void plane_shift(int d, int& o, float& w){
    // disp = linspace(1/50, 1, 8) in f32 ; shift = 76 * disp
    float step = (1.0f - (1.0f/50.0f)) / 7.0f;
    float s = 76.0f * ((1.0f/50.0f) + (float)d * step);
    float fo = floorf(s);
    o = (int)fo;
    w = s - fo;
}

// ---- weight transform: W[co][ci][3][3] -> Wt[tap][ci][co] ----
__global__ void k_wt(const float* __restrict__ W, int sel){
    int i = blockIdx.x*256 + threadIdx.x;
    if(i >= 9*NC*NC) return;
    int co = i & 63, ci = (i>>6) & 63, tap = i >> 12;
    g_Wt[sel][i] = W[(co*NC + ci)*9 + tap];
}

// ---- NCHW -> NHWC (into g_X0) ----
__global__ void k_nchw2nhwc(const float* __restrict__ in){
    __shared__ float t[32][33];
    int b = blockIdx.z / NH, r = blockIdx.z % NH;
    int c0 = blockIdx.x*32, q0 = blockIdx.y*32;
    int tx = threadIdx.x, ty = threadIdx.y;
    #pragma unroll
    for(int j=0;j<32;j+=8)
        t[ty+j][tx] = in[((size_t)(b*NC + q0+ty+j)*NH + r)*NW + c0+tx];
    __syncthreads();
    #pragma unroll
    for(int j=0;j<32;j+=8)
        g_X0[((size_t)(b*NH + r)*NW + c0+ty+j)*NC + q0+tx] = t[tx][ty+j];
}

// ---- NHWC (g_X0) -> NCHW (d_out) ----
__global__ void k_nhwc2nchw(float* __restrict__ out){
    __shared__ float t[32][33];
    int b = blockIdx.z / NH, r = blockIdx.z % NH;
    int c0 = blockIdx.x*32, q0 = blockIdx.y*32;
    int tx = threadIdx.x, ty = threadIdx.y;
    #pragma unroll
    for(int j=0;j<32;j+=8)
        t[ty+j][tx] = g_X0[((size_t)(b*NH + r)*NW + c0+ty+j)*NC + q0+tx];
    __syncthreads();
    #pragma unroll
    for(int j=0;j<32;j+=8)
        out[((size_t)(b*NC + q0+ty+j)*NH + r)*NW + c0+tx] = t[tx][ty+j];
}

// ---- implicit-GEMM conv: M-tile 192, N 64, thread tile 12x8 (FFMA2 along m), 3 blocks/SM ----
// A-tile smem physical col = pixel ^ ((ci_row>>2)*8)  (conflict-free STS + grouped LDS.128)
// B-tile loaded via cp.async (copy-contiguous, no transpose needed)
__global__ void __launch_bounds__(128, 3) k_conv(int inSel, int wSel){
    __shared__ float As[2][16][MTILE];
    __shared__ float Bs[2][16][64];

    const float* __restrict__ X  = (inSel ? g_X1 : g_X0) + (size_t)blockIdx.y*(NH*NW*NC);
    const float* __restrict__ Wt = g_Wt[wSel];
    float* __restrict__ CF = g_CF + (size_t)blockIdx.y*(NHO*NW*NC);

    int m0  = blockIdx.x * MTILE;
    int tid = threadIdx.x;
    int tm = tid >> 3, tn = tid & 7;     // 16 m-groups (12 px each) x 8 n-groups
    int lp  = tid >> 2;                  // gather group 0..31
    int ciq = (tid & 3) * 4;             // ci quad within 16-chunk
    int swz = (tid & 3) * 8;             // store-side XOR ( == (row>>2)*8 )

    unsigned bsmem = smem_u32(&Bs[0][0][0]);

    // packed per-pixel specs for pixels p_j = j*32 + lp, j=0..5
    // spec = pcol(9b) | (pbase+1)(8b)<<9 | pmask(3b)<<17
    unsigned spec[6];
    #pragma unroll
    for(int j=0;j<6;j++){
        int m = m0 + j*32 + lp;
        if(m >= MTOT){ spec[j] = 0; }
        else {
            int row = m / NW, col = m - row*NW;
            int pb, pm;
            if(row < NHC){ pb = row - 1; pm = 7; }
            else {
                int i = row - NHC; int d = i >> 1;
                int o; float w; plane_shift(d, o, w);
                pb = (i & 1) ? o : o - 1;
                pm = 1;
            }
            spec[j] = (unsigned)col | ((unsigned)(pb + 1) << 9) | ((unsigned)pm << 17);
        }
    }

    // accumulators: pairs along m. acc[mp][j] = (C[2mp], C[2mp+1]) for co j, packed f32x2
    unsigned long long acc[6][8];
    #pragma unroll
    for(int i=0;i<6;i++)
        #pragma unroll
        for(int j=0;j<8;j++) acc[i][j] = 0ull;

    float4 ra[6];

    auto gatherA = [&](int kc){
        int tap = kc >> 2, ci0 = (kc & 3) << 4;
        int dy = tap / 3, dx = tap - dy*3;
        #pragma unroll
        for(int j=0;j<6;j++){
            int cc = (int)(spec[j] & 511u) + dx - 1;
            int rr = (int)((spec[j] >> 9) & 255u) - 1 + dy;
            bool v = ((spec[j] >> (17 + dy)) & 1u) && ((unsigned)rr < NH) && ((unsigned)cc < NW);
            if(v) ra[j] = *(const float4*)&X[((size_t)rr*NW + cc)*NC + ci0 + ciq];
            else  ra[j] = make_float4(0.f,0.f,0.f,0.f);
        }
    };
    auto issueB = [&](int kc, int bsel){
        int tap = kc >> 2, ci0 = (kc & 3) << 4;
        const float* src = &Wt[(tap*64 + ci0)*64] + tid*8;
        unsigned dst = bsmem + (unsigned)bsel*4096u + (unsigned)tid*32u;
        asm volatile("cp.async.cg.shared.global [%0], [%1], 16;" :: "r"(dst), "l"(src));
        asm volatile("cp.async.cg.shared.global [%0], [%1], 16;" :: "r"(dst+16u), "l"(src+4));
        asm volatile("cp.async.commit_group;");
    };
    auto storeA = [&](int bsel){
        #pragma unroll
        for(int j=0;j<6;j++){
            int px = (j*32 + lp) ^ swz;
            As[bsel][ciq+0][px] = ra[j].x;
            As[bsel][ciq+1][px] = ra[j].y;
            As[bsel][ciq+2][px] = ra[j].z;
            As[bsel][ciq+3][px] = ra[j].w;
        }
    };

    gatherA(0);
    issueB(0, 0);
    storeA(0);
    asm volatile("cp.async.wait_group 0;" ::: "memory");
    __syncthreads();

    int buf = 0;
    for(int kc=0; kc<36; kc++){
        if(kc < 35){ gatherA(kc+1); issueB(kc+1, buf ^ 1); }
        #pragma unroll
        for(int k=0;k<16;k++){
            const float* arow = &As[buf][k][0];
            int g = (k >> 2) * 8;
            unsigned long long ap[6];
            #pragma unroll
            for(int q=0;q<3;q++){
                // XOR applied per 4-float group
                ulonglong2 t = *(const ulonglong2*)(arow + (((tm*12) + q*4) ^ g));
                ap[q*2]   = t.x;
                ap[q*2+1] = t.y;
            }
            float4 b0 = *(const float4*)&Bs[buf][k][tn*8];
            float4 b1 = *(const float4*)&Bs[buf][k][tn*8 + 4];
            float bv[8] = {b0.x,b0.y,b0.z,b0.w,b1.x,b1.y,b1.z,b1.w};
            #pragma unroll
            for(int j=0;j<8;j++){
                unsigned long long bb;
                unsigned int u = __float_as_uint(bv[j]);
                asm("mov.b64 %0, {%1, %1};" : "=l"(bb) : "r"(u));
                #pragma unroll
                for(int mp=0;mp<6;mp++)
                    asm("fma.rn.f32x2 %0, %1, %2, %0;"
                        : "+l"(acc[mp][j]) : "l"(ap[mp]), "l"(bb));
            }
        }
        if(kc < 35){
            storeA(buf ^ 1);
            asm volatile("cp.async.wait_group 0;" ::: "memory");
            __syncthreads();
            buf ^= 1;
        }
    }

    #pragma unroll
    for(int i=0;i<12;i++){
        int m = m0 + tm*12 + i;
        if(m < MTOT){
            int mp = i >> 1, hi = i & 1;
            float v[8];
            #pragma unroll
            for(int j=0;j<8;j++){
                unsigned long long a = acc[mp][j];
                unsigned int u = hi ? (unsigned int)(a >> 32) : (unsigned int)a;
                v[j] = __uint_as_float(u);
            }
            float* o = &CF[(size_t)m*NC + tn*8];
            *(float4*)(o)   = make_float4(v[0],v[1],v[2],v[3]);
            *(float4*)(o+4) = make_float4(v[4],v[5],v[6],v[7]);
        }
    }
}

// ---- epilogue: 8-plane blend + max + bias + relu ----
// block = (col, batch); 256 threads = 64 co x 4 y-lanes; walks all 96 y (L1 reuse of CF rows)
__global__ void k_epi(const float* __restrict__ bias, int outSel){
    int tid = threadIdx.x;
    int co = tid & 63;
    int yl = tid >> 6;
    int c  = blockIdx.x;
    int b  = blockIdx.y;
    const float* __restrict__ cf = g_CF + (size_t)b*NHO*NW*NC + (size_t)c*NC + co;
    float bv = bias[co];
    const int rstride = NW*NC;
    float* __restrict__ out = outSel ? g_X0 : g_X1;

    for(int y = yl; y < NH; y += 4){
        float mx = -3.4e38f;
        #pragma unroll
        for(int d=0; d<8; d++){
            int o; float w; plane_shift(d, o, w);
            float a = 1.0f - w;
            int t = y + o;
            float v = 0.f;
            if(t <= 96)     v += a * cf[(size_t)t*rstride];
            if(t + 1 <= 96) v += w * cf[(size_t)(t+1)*rstride];
            if(y == 0){
                v -= a * cf[(size_t)(97 + 2*d)*rstride];   // R0[o_d - 1]
                v -= w * cf[(size_t)(98 + 2*d)*rstride];   // R0[o_d]
            }
            mx = fmaxf(mx, v);
        }
        float r = fmaxf(mx + bv, 0.f);
        out[(((size_t)b*NH + y)*NW + c)*NC + co] = r;
    }
}

extern "C" void kernel_launch(void* const* d_in, const int* in_sizes, int n_in,
                              void* d_out, int out_size){
    const float* x  = (const float*)d_in[0];
    const float* W1 = (const float*)d_in[1];
    const float* b1 = (const float*)d_in[2];
    const float* W2 = (const float*)d_in[3];
    const float* b2 = (const float*)d_in[4];
    float* out = (float*)d_out;

    k_wt<<<144, 256>>>(W1, 0);
    k_wt<<<144, 256>>>(W2, 1);
    k_nchw2nhwc<<<dim3(10,2,NB*NH), dim3(32,8)>>>(x);

    k_conv<<<dim3(MBLK, NB), 128>>>(0, 0);        // X0 -> CF (layer 1)
    k_epi <<<dim3(NW, NB), 256>>>(b1, 0);         // CF -> X1

    k_conv<<<dim3(MBLK, NB), 128>>>(1, 1);        // X1 -> CF (layer 2)
    k_epi <<<dim3(NW, NB), 256>>>(b2, 1);         // CF -> X0

    k_nhwc2nchw<<<dim3(10,2,NB*NH), dim3(32,8)>>>(out);
}

// round 16
// speedup vs baseline: 2.0022x; 1.5528x over previous
#include <cuda_runtime.h>
#include <cuda_bf16.h>
#include <math.h>

#define NB 4
#define NC 64
#define NH 96
#define NW 320
#define NHC 97            // CF rows 0..96
#define NHO 113           // 97 CF rows + 16 R0 special rows
#define MTOT (NHO*NW)     // 36160 pixels per batch image
#define MTILE 128
#define MBLK ((MTOT + MTILE - 1)/MTILE)   // 283

// ---------------- global scratch (static; no runtime allocation) ----------------
__device__ float          g_X0[NB*NH*NW*NC];          // final NHWC f32
__device__ __nv_bfloat16  g_Xh[NB*NH*NW*NC];          // activation hi (NHWC bf16)
__device__ __nv_bfloat16  g_Xl[NB*NH*NW*NC];          // activation lo
__device__ float          g_CF[(size_t)NB*NHO*NW*NC]; // conv output f32
__device__ __nv_bfloat16  g_Wb[2][9][2][64*64];       // [layer][tap][hi/lo][co*64+ci]

__device__ __forceinline__ unsigned smem_u32(const void* p){
    unsigned a; asm("{ .reg .u64 t; cvta.to.shared.u64 t, %1; cvt.u32.u64 %0, t; }" : "=r"(a) : "l"(p));
    return a;
}

__device__ __forceinline__ void plane_shift(int d, int& o, float& w){
    float step = (1.0f - (1.0f/50.0f)) / 7.0f;
    float s = 76.0f * ((1.0f/50.0f) + (float)d * step);
    float fo = floorf(s);
    o = (int)fo;
    w = s - fo;
}

__device__ __forceinline__ void mma16816(float* c, const unsigned* a, const unsigned* b){
    asm volatile("mma.sync.aligned.m16n8k16.row.col.f32.bf16.bf16.f32 "
        "{%0,%1,%2,%3}, {%4,%5,%6,%7}, {%8,%9}, {%0,%1,%2,%3};"
        : "+f"(c[0]),"+f"(c[1]),"+f"(c[2]),"+f"(c[3])
        : "r"(a[0]),"r"(a[1]),"r"(a[2]),"r"(a[3]), "r"(b[0]),"r"(b[1]));
}
#define LDSM4(r, addr) \
    asm volatile("ldmatrix.sync.aligned.m8n8.x4.shared.b16 {%0,%1,%2,%3}, [%4];" \
        : "=r"((r)[0]),"=r"((r)[1]),"=r"((r)[2]),"=r"((r)[3]) : "r"(addr))
#define LDS32(r, addr) \
    asm volatile("ld.shared.b32 %0, [%1];" : "=r"(r) : "r"(addr))

// ---- weight transform: W[co][ci][3][3] -> bf16 hi/lo [tap][co][ci] ----
__global__ void k_wt(const float* __restrict__ W, int sel){
    int i = blockIdx.x*256 + threadIdx.x;
    if(i >= 9*64*64) return;
    int k = i & 63, n = (i>>6) & 63, tap = i >> 12;
    float w = W[(n*64 + k)*9 + tap];
    __nv_bfloat16 hi = __float2bfloat16(w);
    __nv_bfloat16 lo = __float2bfloat16(w - __bfloat162float(hi));
    g_Wb[sel][tap][0][n*64 + k] = hi;
    g_Wb[sel][tap][1][n*64 + k] = lo;
}

// ---- NCHW f32 -> NHWC bf16 hi/lo ----
__global__ void k_nchw2nhwc(const float* __restrict__ in){
    __shared__ float t[32][33];
    int b = blockIdx.z / NH, r = blockIdx.z % NH;
    int c0 = blockIdx.x*32, q0 = blockIdx.y*32;
    int tx = threadIdx.x, ty = threadIdx.y;
    #pragma unroll
    for(int j=0;j<32;j+=8)
        t[ty+j][tx] = in[((size_t)(b*NC + q0+ty+j)*NH + r)*NW + c0+tx];
    __syncthreads();
    #pragma unroll
    for(int j=0;j<32;j+=8){
        float v = t[tx][ty+j];
        size_t idx = ((size_t)(b*NH + r)*NW + c0+ty+j)*NC + q0+tx;
        __nv_bfloat16 hi = __float2bfloat16(v);
        g_Xh[idx] = hi;
        g_Xl[idx] = __float2bfloat16(v - __bfloat162float(hi));
    }
}

// ---- NHWC f32 (g_X0) -> NCHW f32 (d_out) ----
__global__ void k_nhwc2nchw(float* __restrict__ out){
    __shared__ float t[32][33];
    int b = blockIdx.z / NH, r = blockIdx.z % NH;
    int c0 = blockIdx.x*32, q0 = blockIdx.y*32;
    int tx = threadIdx.x, ty = threadIdx.y;
    #pragma unroll
    for(int j=0;j<32;j+=8)
        t[ty+j][tx] = g_X0[((size_t)(b*NH + r)*NW + c0+ty+j)*NC + q0+tx];
    __syncthreads();
    #pragma unroll
    for(int j=0;j<32;j+=8)
        out[((size_t)(b*NC + q0+ty+j)*NH + r)*NW + c0+tx] = t[tx][ty+j];
}

// ---------------- HMMA implicit-GEMM conv ----------------
// Tile M=128 px, N=64 co; per tap K=64, 9 taps; bf16 hi/lo (3 mma combos).
// smem per buffer: Ah 16K | Al 16K | Bh 9216 | Bl 9216 = 51200; double-buffered.
// A layout: [128 px][8 chunks of 16B], phys chunk = c ^ (px&7)  (conflict-free STS.128 + ldmatrix)
// B layout: [64 n][72 k bf16] (144B row, 16B-aligned; frag lds.b32 conflict-free)
#define OFF_AL 16384
#define OFF_BH 32768
#define OFF_BL 41984
#define BUFSZ  51200
#define SMEM_CONV (2*BUFSZ)

__global__ void __launch_bounds__(128, 2) k_conv(int layer){
    extern __shared__ char smem[];
    unsigned sb = smem_u32(smem);
    const __nv_bfloat16* __restrict__ Xh = g_Xh + (size_t)blockIdx.y*(NH*NW*NC);
    const __nv_bfloat16* __restrict__ Xl = g_Xl + (size_t)blockIdx.y*(NH*NW*NC);
    float* __restrict__ CF = g_CF + (size_t)blockIdx.y*(NHO*NW*NC);

    int m0  = blockIdx.x * MTILE;
    int tid = threadIdx.x, w = tid >> 5, l = tid & 31;

    // ---- per-pixel gather specs: pixel p_i = w*32 + i*4 + (l>>3), chunk = l&7 ----
    unsigned spec[8];
    #pragma unroll
    for(int i=0;i<8;i++){
        int p = w*32 + i*4 + (l>>3);
        int m = m0 + p;
        if(m >= MTOT){ spec[i] = 0; }
        else {
            int row = m / NW, col = m - row*NW;
            int pb, pm;
            if(row < NHC){ pb = row - 1; pm = 7; }
            else {
                int i2 = row - NHC; int d = i2 >> 1;
                int o; float wf; plane_shift(d, o, wf);
                pb = (i2 & 1) ? o : o - 1;
                pm = 1;
            }
            spec[i] = (unsigned)col | ((unsigned)(pb + 1) << 9) | ((unsigned)pm << 17);
        }
    }

    // ---- ldmatrix row precompute (A frags) ----
    int rA[2], rlow[2];
    #pragma unroll
    for(int mt=0;mt<2;mt++){
        int r = w*32 + mt*16 + (l & 7) + ((l >> 3) & 1)*8;
        rA[mt] = r*128;
        rlow[mt] = r & 7;
    }
    int kc8 = l >> 4;
    // B frag per-lane base: n = l>>2 row, k = (l&3)*2
    unsigned bfb = (unsigned)((l >> 2)*144 + (l & 3)*4);

    float c[2][8][4];
    #pragma unroll
    for(int mt=0;mt<2;mt++)
        #pragma unroll
        for(int nt=0;nt<8;nt++)
            #pragma unroll
            for(int q=0;q<4;q++) c[mt][nt][q] = 0.f;

    const __nv_bfloat16* __restrict__ WbH = &g_Wb[layer][0][0][0];

    auto gather = [&](int tap, int bsel){
        int dy = tap / 3, dx = tap - dy*3 - 1;
        char* abase = smem + bsel*BUFSZ;
        int c7 = l & 7;
        #pragma unroll
        for(int i=0;i<8;i++){
            int p = w*32 + i*4 + (l>>3);
            int cc = (int)(spec[i] & 511u) + dx;
            int rr = (int)((spec[i] >> 9) & 255u) - 1 + dy;
            bool v = ((spec[i] >> (17 + dy)) & 1u) && ((unsigned)rr < NH) && ((unsigned)cc < NW);
            uint4 vh = make_uint4(0,0,0,0), vl = make_uint4(0,0,0,0);
            if(v){
                size_t off = ((size_t)rr*NW + cc)*NC + c7*8;
                vh = *(const uint4*)(Xh + off);
                vl = *(const uint4*)(Xl + off);
            }
            unsigned dst = (unsigned)(p*128 + ((c7 ^ (p & 7))*16));
            *(uint4*)(abase + dst)          = vh;
            *(uint4*)(abase + OFF_AL + dst) = vl;
        }
        // B: [64 n][72 k] padded copy, hi+lo (tap slice)
        int n = tid >> 1, j = tid & 1;
        const uint4* sh = (const uint4*)(WbH + ((size_t)tap*2 + 0)*4096 + n*64 + j*32);
        const uint4* sl = (const uint4*)(WbH + ((size_t)tap*2 + 1)*4096 + n*64 + j*32);
        uint4* dh = (uint4*)(abase + OFF_BH + n*144 + j*64);
        uint4* dl = (uint4*)(abase + OFF_BL + n*144 + j*64);
        #pragma unroll
        for(int s=0;s<4;s++){ dh[s] = sh[s]; dl[s] = sl[s]; }
    };

    auto compute = [&](int bsel){
        unsigned abase = sb + (unsigned)(bsel*BUFSZ);
        #pragma unroll
        for(int kc=0; kc<4; kc++){
            unsigned ah[2][4], al[2][4];
            #pragma unroll
            for(int mt=0;mt<2;mt++){
                unsigned ca = abase + (unsigned)rA[mt] + (unsigned)((((kc*2 + kc8) ^ rlow[mt]))*16);
                LDSM4(ah[mt], ca);
                LDSM4(al[mt], ca + OFF_AL);
            }
            unsigned bh[8][2], bl[8][2];
            unsigned bb = abase + OFF_BH + bfb + (unsigned)(kc*32);
            #pragma unroll
            for(int nt=0;nt<8;nt++){
                unsigned a0 = bb + (unsigned)(nt*8*144);
                LDS32(bh[nt][0], a0);
                LDS32(bh[nt][1], a0 + 16);
                LDS32(bl[nt][0], a0 + (OFF_BL - OFF_BH));
                LDS32(bl[nt][1], a0 + (OFF_BL - OFF_BH) + 16);
            }
            #pragma unroll
            for(int mt=0;mt<2;mt++)
                #pragma unroll
                for(int nt=0;nt<8;nt++){
                    mma16816(c[mt][nt], ah[mt], bh[nt]);
                    mma16816(c[mt][nt], al[mt], bh[nt]);
                    mma16816(c[mt][nt], ah[mt], bl[nt]);
                }
        }
    };

    gather(0, 0);
    __syncthreads();

    int buf = 0;
    for(int t=0; t<9; t++){
        if(t < 8) gather(t+1, buf ^ 1);
        compute(buf);
        __syncthreads();
        buf ^= 1;
    }

    // ---- store C -> CF ----
    #pragma unroll
    for(int mt=0;mt<2;mt++){
        int R0 = w*32 + mt*16 + (l >> 2);
        #pragma unroll
        for(int nt=0;nt<8;nt++){
            int col = nt*8 + (l & 3)*2;
            int mA = m0 + R0;
            int mB = mA + 8;
            if(mA < MTOT) *(float2*)&CF[(size_t)mA*NC + col] = make_float2(c[mt][nt][0], c[mt][nt][1]);
            if(mB < MTOT) *(float2*)&CF[(size_t)mB*NC + col] = make_float2(c[mt][nt][2], c[mt][nt][3]);
        }
    }
}

// ---- epilogue: 8-plane blend + max + bias + relu ----
// block = (col, batch); 256 threads = 64 co x 4 y-lanes; walks all 96 y (L1 reuse of CF rows)
__global__ void k_epi(const float* __restrict__ bias, int mode){
    int tid = threadIdx.x;
    int co = tid & 63;
    int yl = tid >> 6;
    int cc = blockIdx.x;
    int b  = blockIdx.y;
    const float* __restrict__ cf = g_CF + (size_t)b*NHO*NW*NC + (size_t)cc*NC + co;
    float bv = bias[co];
    const int rstride = NW*NC;

    for(int y = yl; y < NH; y += 4){
        float mx = -3.4e38f;
        #pragma unroll
        for(int d=0; d<8; d++){
            int o; float w; plane_shift(d, o, w);
            float a = 1.0f - w;
            int t = y + o;
            float v = 0.f;
            if(t <= 96)     v += a * cf[(size_t)t*rstride];
            if(t + 1 <= 96) v += w * cf[(size_t)(t+1)*rstride];
            if(y == 0){
                v -= a * cf[(size_t)(97 + 2*d)*rstride];   // R0[o_d - 1]
                v -= w * cf[(size_t)(98 + 2*d)*rstride];   // R0[o_d]
            }
            mx = fmaxf(mx, v);
        }
        float r = fmaxf(mx + bv, 0.f);
        size_t idx = (((size_t)b*NH + y)*NW + cc)*NC + co;
        if(mode == 0){
            __nv_bfloat16 hi = __float2bfloat16(r);
            g_Xh[idx] = hi;
            g_Xl[idx] = __float2bfloat16(r - __bfloat162float(hi));
        }else{
            g_X0[idx] = r;
        }
    }
}

extern "C" void kernel_launch(void* const* d_in, const int* in_sizes, int n_in,
                              void* d_out, int out_size){
    const float* x  = (const float*)d_in[0];
    const float* W1 = (const float*)d_in[1];
    const float* b1 = (const float*)d_in[2];
    const float* W2 = (const float*)d_in[3];
    const float* b2 = (const float*)d_in[4];
    float* out = (float*)d_out;

    cudaFuncSetAttribute(k_conv, cudaFuncAttributeMaxDynamicSharedMemorySize, SMEM_CONV);

    k_wt<<<144, 256>>>(W1, 0);
    k_wt<<<144, 256>>>(W2, 1);
    k_nchw2nhwc<<<dim3(10,2,NB*NH), dim3(32,8)>>>(x);

    k_conv<<<dim3(MBLK, NB), 128, SMEM_CONV>>>(0);  // Xh/Xl -> CF (layer 1)
    k_epi <<<dim3(NW, NB), 256>>>(b1, 0);           // CF -> Xh/Xl

    k_conv<<<dim3(MBLK, NB), 128, SMEM_CONV>>>(1);  // Xh/Xl -> CF (layer 2)
    k_epi <<<dim3(NW, NB), 256>>>(b2, 1);           // CF -> X0 (f32)

    k_nhwc2nchw<<<dim3(10,2,NB*NH), dim3(32,8)>>>(out);
}

// round 17
// speedup vs baseline: 2.1632x; 1.0804x over previous
#include <cuda_runtime.h>
#include <cuda_bf16.h>
#include <math.h>

#define NB 4
#define NC 64
#define NH 96
#define NW 320
#define NHC 97            // CF rows 0..96
#define NHO 113           // 97 CF rows + 16 R0 special rows
#define MTOT (NHO*NW)     // 36160 pixels per batch image
#define MTILE 128
#define MBLK ((MTOT + MTILE - 1)/MTILE)   // 283

// ---------------- global scratch (static; no runtime allocation) ----------------
__device__ float          g_X0[NB*NH*NW*NC];          // final NHWC f32
__device__ __nv_bfloat16  g_Xh[NB*NH*NW*NC];          // activation hi (NHWC bf16)
__device__ __nv_bfloat16  g_Xl[NB*NH*NW*NC];          // activation lo
__device__ float          g_CF[(size_t)NB*NHO*NW*NC]; // conv output f32
__device__ __nv_bfloat16  g_Wb[2][9][2][64*64];       // [layer][tap][hi/lo][co*64+ci]

__device__ __forceinline__ unsigned smem_u32(const void* p){
    unsigned a; asm("{ .reg .u64 t; cvta.to.shared.u64 t, %1; cvt.u32.u64 %0, t; }" : "=r"(a) : "l"(p));
    return a;
}

__device__ __forceinline__ void plane_shift(int d, int& o, float& w){
    float step = (1.0f - (1.0f/50.0f)) / 7.0f;
    float s = 76.0f * ((1.0f/50.0f) + (float)d * step);
    float fo = floorf(s);
    o = (int)fo;
    w = s - fo;
}

__device__ __forceinline__ void mma16816(float* c, const unsigned* a, const unsigned* b){
    asm volatile("mma.sync.aligned.m16n8k16.row.col.f32.bf16.bf16.f32 "
        "{%0,%1,%2,%3}, {%4,%5,%6,%7}, {%8,%9}, {%0,%1,%2,%3};"
        : "+f"(c[0]),"+f"(c[1]),"+f"(c[2]),"+f"(c[3])
        : "r"(a[0]),"r"(a[1]),"r"(a[2]),"r"(a[3]), "r"(b[0]),"r"(b[1]));
}
#define LDSM4(r, addr) \
    asm volatile("ldmatrix.sync.aligned.m8n8.x4.shared.b16 {%0,%1,%2,%3}, [%4];" \
        : "=r"((r)[0]),"=r"((r)[1]),"=r"((r)[2]),"=r"((r)[3]) : "r"(addr))
#define LDS32(r, addr) \
    asm volatile("ld.shared.b32 %0, [%1];" : "=r"(r) : "r"(addr))
#define CP16(dst, src, sz) \
    asm volatile("cp.async.cg.shared.global [%0], [%1], 16, %2;" :: "r"(dst), "l"(src), "r"(sz))
#define CP16F(dst, src) \
    asm volatile("cp.async.cg.shared.global [%0], [%1], 16;" :: "r"(dst), "l"(src))
#define CP_COMMIT() asm volatile("cp.async.commit_group;")
#define CP_WAIT0()  asm volatile("cp.async.wait_group 0;" ::: "memory")

// ---- weight transform: W[co][ci][3][3] -> bf16 hi/lo [tap][co][ci] ----
__global__ void k_wt(const float* __restrict__ W, int sel){
    int i = blockIdx.x*256 + threadIdx.x;
    if(i >= 9*64*64) return;
    int k = i & 63, n = (i>>6) & 63, tap = i >> 12;
    float w = W[(n*64 + k)*9 + tap];
    __nv_bfloat16 hi = __float2bfloat16(w);
    __nv_bfloat16 lo = __float2bfloat16(w - __bfloat162float(hi));
    g_Wb[sel][tap][0][n*64 + k] = hi;
    g_Wb[sel][tap][1][n*64 + k] = lo;
}

// ---- NCHW f32 -> NHWC bf16 hi/lo ----
__global__ void k_nchw2nhwc(const float* __restrict__ in){
    __shared__ float t[32][33];
    int b = blockIdx.z / NH, r = blockIdx.z % NH;
    int c0 = blockIdx.x*32, q0 = blockIdx.y*32;
    int tx = threadIdx.x, ty = threadIdx.y;
    #pragma unroll
    for(int j=0;j<32;j+=8)
        t[ty+j][tx] = in[((size_t)(b*NC + q0+ty+j)*NH + r)*NW + c0+tx];
    __syncthreads();
    #pragma unroll
    for(int j=0;j<32;j+=8){
        float v = t[tx][ty+j];
        size_t idx = ((size_t)(b*NH + r)*NW + c0+ty+j)*NC + q0+tx;
        __nv_bfloat16 hi = __float2bfloat16(v);
        g_Xh[idx] = hi;
        g_Xl[idx] = __float2bfloat16(v - __bfloat162float(hi));
    }
}

// ---- NHWC f32 (g_X0) -> NCHW f32 (d_out) ----
__global__ void k_nhwc2nchw(float* __restrict__ out){
    __shared__ float t[32][33];
    int b = blockIdx.z / NH, r = blockIdx.z % NH;
    int c0 = blockIdx.x*32, q0 = blockIdx.y*32;
    int tx = threadIdx.x, ty = threadIdx.y;
    #pragma unroll
    for(int j=0;j<32;j+=8)
        t[ty+j][tx] = g_X0[((size_t)(b*NH + r)*NW + c0+ty+j)*NC + q0+tx];
    __syncthreads();
    #pragma unroll
    for(int j=0;j<32;j+=8)
        out[((size_t)(b*NC + q0+ty+j)*NH + r)*NW + c0+tx] = t[tx][ty+j];
}

// ---------------- HMMA implicit-GEMM conv (cp.async zfill gather) ----------------
// Tile M=128 px, N=64 co; per tap K=64, 9 taps; bf16 hi/lo (3 mma combos).
// smem per buffer: Ah 16K | Al 16K | Bh 9216 | Bl 9216 = 51200; double-buffered.
// A layout: [128 px][8 chunks of 16B], phys chunk = c ^ (px&7)  (conflict-free STS + ldmatrix)
// B layout: [64 n][72 k bf16] (144B row, 16B-aligned; frag lds.b32 conflict-free)
#define OFF_AL 16384
#define OFF_BH 32768
#define OFF_BL 41984
#define BUFSZ  51200
#define SMEM_CONV (2*BUFSZ)

__global__ void __launch_bounds__(128, 2) k_conv(int layer){
    extern __shared__ char smem[];
    unsigned sb = smem_u32(smem);
    const __nv_bfloat16* __restrict__ Xh = g_Xh + (size_t)blockIdx.y*(NH*NW*NC);
    const __nv_bfloat16* __restrict__ Xl = g_Xl + (size_t)blockIdx.y*(NH*NW*NC);
    float* __restrict__ CF = g_CF + (size_t)blockIdx.y*(NHO*NW*NC);

    int m0  = blockIdx.x * MTILE;
    int tid = threadIdx.x, w = tid >> 5, l = tid & 31;

    // ---- per-pixel gather specs: pixel p_i = w*32 + i*4 + (l>>3), chunk = l&7 ----
    unsigned spec[8];
    #pragma unroll
    for(int i=0;i<8;i++){
        int p = w*32 + i*4 + (l>>3);
        int m = m0 + p;
        if(m >= MTOT){ spec[i] = 0; }
        else {
            int row = m / NW, col = m - row*NW;
            int pb, pm;
            if(row < NHC){ pb = row - 1; pm = 7; }
            else {
                int i2 = row - NHC; int d = i2 >> 1;
                int o; float wf; plane_shift(d, o, wf);
                pb = (i2 & 1) ? o : o - 1;
                pm = 1;
            }
            spec[i] = (unsigned)col | ((unsigned)(pb + 1) << 9) | ((unsigned)pm << 17);
        }
    }

    // ---- ldmatrix row precompute (A frags) ----
    int rA[2], rlow[2];
    #pragma unroll
    for(int mt=0;mt<2;mt++){
        int r = w*32 + mt*16 + (l & 7) + ((l >> 3) & 1)*8;
        rA[mt] = r*128;
        rlow[mt] = r & 7;
    }
    int kc8 = l >> 4;
    // B frag per-lane base: n = l>>2 row, k = (l&3)*2
    unsigned bfb = (unsigned)((l >> 2)*144 + (l & 3)*4);

    float c[2][8][4];
    #pragma unroll
    for(int mt=0;mt<2;mt++)
        #pragma unroll
        for(int nt=0;nt<8;nt++)
            #pragma unroll
            for(int q=0;q<4;q++) c[mt][nt][q] = 0.f;

    const __nv_bfloat16* __restrict__ WbH = &g_Wb[layer][0][0][0];

    // fully-async gather: cp.async with src_size 0 => zero-fill (boundary mask in the copy unit)
    auto gather = [&](int tap, int bsel){
        int dy = tap / 3, dx = tap - dy*3 - 1;
        unsigned abase = sb + (unsigned)(bsel*BUFSZ);
        int c7 = l & 7;
        #pragma unroll
        for(int i=0;i<8;i++){
            int p = w*32 + i*4 + (l>>3);
            int cc = (int)(spec[i] & 511u) + dx;
            int rr = (int)((spec[i] >> 9) & 255u) - 1 + dy;
            bool v = ((spec[i] >> (17 + dy)) & 1u) && ((unsigned)rr < NH) && ((unsigned)cc < NW);
            size_t off = v ? (((size_t)rr*NW + cc)*NC + c7*8) : 0;
            unsigned sz = v ? 16u : 0u;
            unsigned dst = abase + (unsigned)(p*128 + ((c7 ^ (p & 7))*16));
            CP16(dst,          Xh + off, sz);
            CP16(dst + OFF_AL, Xl + off, sz);
        }
        // B: [64 n][72 k] padded copy, hi+lo (tap slice)
        int n = tid >> 1, j = tid & 1;
        const __nv_bfloat16* sh = WbH + ((size_t)tap*2 + 0)*4096 + n*64 + j*32;
        const __nv_bfloat16* sl = WbH + ((size_t)tap*2 + 1)*4096 + n*64 + j*32;
        unsigned dh = abase + (unsigned)(OFF_BH + n*144 + j*64);
        unsigned dl = abase + (unsigned)(OFF_BL + n*144 + j*64);
        #pragma unroll
        for(int s=0;s<4;s++){
            CP16F(dh + s*16u, sh + s*8);
            CP16F(dl + s*16u, sl + s*8);
        }
        CP_COMMIT();
    };

    auto compute = [&](int bsel){
        unsigned abase = sb + (unsigned)(bsel*BUFSZ);
        #pragma unroll
        for(int kc=0; kc<4; kc++){
            unsigned ah[2][4], al[2][4];
            #pragma unroll
            for(int mt=0;mt<2;mt++){
                unsigned ca = abase + (unsigned)rA[mt] + (unsigned)((((kc*2 + kc8) ^ rlow[mt]))*16);
                LDSM4(ah[mt], ca);
                LDSM4(al[mt], ca + OFF_AL);
            }
            unsigned bh[8][2], bl[8][2];
            unsigned bb = abase + OFF_BH + bfb + (unsigned)(kc*32);
            #pragma unroll
            for(int nt=0;nt<8;nt++){
                unsigned a0 = bb + (unsigned)(nt*8*144);
                LDS32(bh[nt][0], a0);
                LDS32(bh[nt][1], a0 + 16);
                LDS32(bl[nt][0], a0 + (OFF_BL - OFF_BH));
                LDS32(bl[nt][1], a0 + (OFF_BL - OFF_BH) + 16);
            }
            #pragma unroll
            for(int mt=0;mt<2;mt++)
                #pragma unroll
                for(int nt=0;nt<8;nt++){
                    mma16816(c[mt][nt], ah[mt], bh[nt]);
                    mma16816(c[mt][nt], al[mt], bh[nt]);
                    mma16816(c[mt][nt], ah[mt], bl[nt]);
                }
        }
    };

    gather(0, 0);
    CP_WAIT0();
    __syncthreads();

    int buf = 0;
    for(int t=0; t<9; t++){
        if(t < 8) gather(t+1, buf ^ 1);   // pure async issue; no warp stall
        compute(buf);
        if(t < 8) CP_WAIT0();
        __syncthreads();
        buf ^= 1;
    }

    // ---- store C -> CF ----
    #pragma unroll
    for(int mt=0;mt<2;mt++){
        int R0 = w*32 + mt*16 + (l >> 2);
        #pragma unroll
        for(int nt=0;nt<8;nt++){
            int col = nt*8 + (l & 3)*2;
            int mA = m0 + R0;
            int mB = mA + 8;
            if(mA < MTOT) *(float2*)&CF[(size_t)mA*NC + col] = make_float2(c[mt][nt][0], c[mt][nt][1]);
            if(mB < MTOT) *(float2*)&CF[(size_t)mB*NC + col] = make_float2(c[mt][nt][2], c[mt][nt][3]);
        }
    }
}

// ---- epilogue: 8-plane blend + max + bias + relu ----
// block = (col, batch); 256 threads = 64 co x 4 y-lanes; walks all 96 y (L1 reuse of CF rows)
__global__ void k_epi(const float* __restrict__ bias, int mode){
    int tid = threadIdx.x;
    int co = tid & 63;
    int yl = tid >> 6;
    int cc = blockIdx.x;
    int b  = blockIdx.y;
    const float* __restrict__ cf = g_CF + (size_t)b*NHO*NW*NC + (size_t)cc*NC + co;
    float bv = bias[co];
    const int rstride = NW*NC;

    for(int y = yl; y < NH; y += 4){
        float mx = -3.4e38f;
        #pragma unroll
        for(int d=0; d<8; d++){
            int o; float w; plane_shift(d, o, w);
            float a = 1.0f - w;
            int t = y + o;
            float v = 0.f;
            if(t <= 96)     v += a * cf[(size_t)t*rstride];
            if(t + 1 <= 96) v += w * cf[(size_t)(t+1)*rstride];
            if(y == 0){
                v -= a * cf[(size_t)(97 + 2*d)*rstride];   // R0[o_d - 1]
                v -= w * cf[(size_t)(98 + 2*d)*rstride];   // R0[o_d]
            }
            mx = fmaxf(mx, v);
        }
        float r = fmaxf(mx + bv, 0.f);
        size_t idx = (((size_t)b*NH + y)*NW + cc)*NC + co;
        if(mode == 0){
            __nv_bfloat16 hi = __float2bfloat16(r);
            g_Xh[idx] = hi;
            g_Xl[idx] = __float2bfloat16(r - __bfloat162float(hi));
        }else{
            g_X0[idx] = r;
        }
    }
}

extern "C" void kernel_launch(void* const* d_in, const int* in_sizes, int n_in,
                              void* d_out, int out_size){
    const float* x  = (const float*)d_in[0];
    const float* W1 = (const float*)d_in[1];
    const float* b1 = (const float*)d_in[2];
    const float* W2 = (const float*)d_in[3];
    const float* b2 = (const float*)d_in[4];
    float* out = (float*)d_out;

    cudaFuncSetAttribute(k_conv, cudaFuncAttributeMaxDynamicSharedMemorySize, SMEM_CONV);

    k_wt<<<144, 256>>>(W1, 0);
    k_wt<<<144, 256>>>(W2, 1);
    k_nchw2nhwc<<<dim3(10,2,NB*NH), dim3(32,8)>>>(x);

    k_conv<<<dim3(MBLK, NB), 128, SMEM_CONV>>>(0);  // Xh/Xl -> CF (layer 1)
    k_epi <<<dim3(NW, NB), 256>>>(b1, 0);           // CF -> Xh/Xl

    k_conv<<<dim3(MBLK, NB), 128, SMEM_CONV>>>(1);  // Xh/Xl -> CF (layer 2)
    k_epi <<<dim3(NW, NB), 256>>>(b2, 1);           // CF -> X0 (f32)

    k_nhwc2nchw<<<dim3(10,2,NB*NH), dim3(32,8)>>>(out);
}